// round 1
// baseline (speedup 1.0000x reference)
#include <cuda_runtime.h>
#include <math.h>

// ---------------- problem constants ----------------
constexpr int Bv = 8, Tv = 8, Hv = 56, Wv = 56, Cv = 192;
constexpr int WSv = 7, NHv = 6, Lv = Hv * Wv;       // 3136
constexpr int HIDv = 4 * Cv;                        // 768
constexpr int Mv = Bv * Tv * Lv;                    // 200704 tokens
constexpr int Dv = Cv / NHv;                        // 32 head dim
constexpr long MCl = (long)Mv * Cv;                 // 38,535,168
constexpr float QSCALE = 0.17677669529663687f;      // 32^-0.5

// ---------------- device scratch (no cudaMalloc allowed) ----------------
__device__ float g_mean1[Mv];
__device__ float g_rstd1[Mv];
__device__ float g_mean2t[Mv];
__device__ float g_rstd2t[Mv];
__device__ float g_mean2s[Mv];
__device__ float g_rstd2s[Mv];
__device__ float g_qkv[(long)Mv * 576];   // q|k|v per token (q pre-scaled)
__device__ float g_osp[MCl];              // spatial attention output
__device__ float g_ot[MCl];               // temporal attention output
__device__ float g_h[(long)Mv * HIDv];    // MLP hidden (reused by both branches)
__device__ float g_xt_fb[MCl];            // fallback if d_out only holds 'out'
__device__ float g_xsp_fb[MCl];

// ---------------- LN statistics (mean + rstd per token, two-pass) ----------------
__global__ void ln_stats_kernel(const float* __restrict__ X,
                                float* __restrict__ mean, float* __restrict__ rstd) {
    int tok = blockIdx.x * 8 + (threadIdx.x >> 5);
    int lane = threadIdx.x & 31;
    const float* p = X + (long)tok * Cv;
    float v[6];
#pragma unroll
    for (int i = 0; i < 6; i++) v[i] = p[lane + i * 32];
    float s = v[0] + v[1] + v[2] + v[3] + v[4] + v[5];
#pragma unroll
    for (int o = 16; o > 0; o >>= 1) s += __shfl_xor_sync(~0u, s, o);
    float mu = s * (1.0f / Cv);
    float q = 0.f;
#pragma unroll
    for (int i = 0; i < 6; i++) { float d = v[i] - mu; q += d * d; }
#pragma unroll
    for (int o = 16; o > 0; o >>= 1) q += __shfl_xor_sync(~0u, q, o);
    if (lane == 0) {
        mean[tok] = mu;
        rstd[tok] = rsqrtf(q * (1.0f / Cv) + 1e-5f);
    }
}

// ---------------- generic fused GEMM: Y = f(A') @ W^T + bias, epilogue ----------------
// A modes: 0 plain; 1 layernorm((A-mean)*rstd*gamma+beta); 2 concat(A | A2) along K
// E modes: 0 bias; 1 bias + q-scale for cols<192; 2 bias + residual R; 3 bias + exact GELU
constexpr int GBM = 128, GBN = 64, GBK = 16;

template <int KD, int AM, int EM>
__global__ void __launch_bounds__(256, 2)
gemm_kernel(const float* __restrict__ A, const float* __restrict__ A2,
            const float* __restrict__ W, const float* __restrict__ bias,
            const float* __restrict__ mean, const float* __restrict__ rstd,
            const float* __restrict__ gamma, const float* __restrict__ beta,
            const float* R, float* Y, int N) {
    __shared__ float As[2][GBK][GBM];
    __shared__ float Bs[2][GBK][GBN];
    const int tid = threadIdx.x;
    const long m0 = (long)blockIdx.x * GBM;
    const int n0 = blockIdx.y * GBN;
    const int KT = KD / GBK;

    const int am0 = tid >> 2;                 // rows 0..63
    const int am1 = (tid + 256) >> 2;         // rows 64..127
    const int akq = (tid & 3) * 4;            // k quad within tile
    const int bn = tid >> 2;                  // 0..63
    const int bkq = (tid & 3) * 4;

    float lnmu0 = 0.f, lnrs0 = 0.f, lnmu1 = 0.f, lnrs1 = 0.f;
    if (AM == 1) {
        lnmu0 = mean[m0 + am0]; lnrs0 = rstd[m0 + am0];
        lnmu1 = mean[m0 + am1]; lnrs1 = rstd[m0 + am1];
    }

    float4 ra0, ra1, rb;

    auto gload = [&](int kt) {
        int kg = kt * GBK + akq;
        const float *s0, *s1;
        if (AM == 2) {
            s0 = (kg < 192) ? (A + (m0 + am0) * 192 + kg) : (A2 + (m0 + am0) * 192 + (kg - 192));
            s1 = (kg < 192) ? (A + (m0 + am1) * 192 + kg) : (A2 + (m0 + am1) * 192 + (kg - 192));
        } else {
            s0 = A + (m0 + am0) * KD + kg;
            s1 = A + (m0 + am1) * KD + kg;
        }
        ra0 = *reinterpret_cast<const float4*>(s0);
        ra1 = *reinterpret_cast<const float4*>(s1);
        if (AM == 1) {
            float g0 = gamma[kg + 0], g1 = gamma[kg + 1], g2 = gamma[kg + 2], g3 = gamma[kg + 3];
            float b0 = beta[kg + 0], b1 = beta[kg + 1], b2 = beta[kg + 2], b3 = beta[kg + 3];
            ra0.x = (ra0.x - lnmu0) * lnrs0 * g0 + b0;
            ra0.y = (ra0.y - lnmu0) * lnrs0 * g1 + b1;
            ra0.z = (ra0.z - lnmu0) * lnrs0 * g2 + b2;
            ra0.w = (ra0.w - lnmu0) * lnrs0 * g3 + b3;
            ra1.x = (ra1.x - lnmu1) * lnrs1 * g0 + b0;
            ra1.y = (ra1.y - lnmu1) * lnrs1 * g1 + b1;
            ra1.z = (ra1.z - lnmu1) * lnrs1 * g2 + b2;
            ra1.w = (ra1.w - lnmu1) * lnrs1 * g3 + b3;
        }
        rb = *reinterpret_cast<const float4*>(W + (long)(n0 + bn) * KD + kg);
    };
    auto sstore = [&](int buf) {
        As[buf][akq + 0][am0] = ra0.x; As[buf][akq + 1][am0] = ra0.y;
        As[buf][akq + 2][am0] = ra0.z; As[buf][akq + 3][am0] = ra0.w;
        As[buf][akq + 0][am1] = ra1.x; As[buf][akq + 1][am1] = ra1.y;
        As[buf][akq + 2][am1] = ra1.z; As[buf][akq + 3][am1] = ra1.w;
        Bs[buf][bkq + 0][bn] = rb.x; Bs[buf][bkq + 1][bn] = rb.y;
        Bs[buf][bkq + 2][bn] = rb.z; Bs[buf][bkq + 3][bn] = rb.w;
    };

    gload(0); sstore(0);
    __syncthreads();

    const int ty = tid >> 4, tx = tid & 15;

    unsigned long long acc[4][4];  // f32x2 pairs: rows (ty*8+2i, ty*8+2i+1) x 4 cols
#pragma unroll
    for (int i = 0; i < 4; i++)
#pragma unroll
        for (int j = 0; j < 4; j++) acc[i][j] = 0ull;

    for (int kt = 0; kt < KT; kt++) {
        int cur = kt & 1;
        if (kt + 1 < KT) gload(kt + 1);
#pragma unroll
        for (int kk = 0; kk < GBK; kk++) {
            const unsigned long long* ap =
                reinterpret_cast<const unsigned long long*>(&As[cur][kk][ty * 8]);
            unsigned long long a0 = ap[0], a1 = ap[1], a2 = ap[2], a3 = ap[3];
            float4 bv = *reinterpret_cast<const float4*>(&Bs[cur][kk][tx * 4]);
            unsigned long long b0, b1, b2, b3;
            asm("mov.b64 %0, {%1,%1};" : "=l"(b0) : "r"(__float_as_uint(bv.x)));
            asm("mov.b64 %0, {%1,%1};" : "=l"(b1) : "r"(__float_as_uint(bv.y)));
            asm("mov.b64 %0, {%1,%1};" : "=l"(b2) : "r"(__float_as_uint(bv.z)));
            asm("mov.b64 %0, {%1,%1};" : "=l"(b3) : "r"(__float_as_uint(bv.w)));
#define FF2(i, j, aa, bb) \
    asm("fma.rn.f32x2 %0, %1, %2, %0;" : "+l"(acc[i][j]) : "l"(aa), "l"(bb));
            FF2(0, 0, a0, b0) FF2(0, 1, a0, b1) FF2(0, 2, a0, b2) FF2(0, 3, a0, b3)
            FF2(1, 0, a1, b0) FF2(1, 1, a1, b1) FF2(1, 2, a1, b2) FF2(1, 3, a1, b3)
            FF2(2, 0, a2, b0) FF2(2, 1, a2, b1) FF2(2, 2, a2, b2) FF2(2, 3, a2, b3)
            FF2(3, 0, a3, b0) FF2(3, 1, a3, b1) FF2(3, 2, a3, b2) FF2(3, 3, a3, b3)
#undef FF2
        }
        if (kt + 1 < KT) sstore(cur ^ 1);
        __syncthreads();
    }

    // unpack accumulators
    float accf[8][4];
#pragma unroll
    for (int ip = 0; ip < 4; ip++)
#pragma unroll
        for (int j = 0; j < 4; j++) {
            unsigned int lo, hi;
            asm("mov.b64 {%0,%1}, %2;" : "=r"(lo), "=r"(hi) : "l"(acc[ip][j]));
            accf[ip * 2 + 0][j] = __uint_as_float(lo);
            accf[ip * 2 + 1][j] = __uint_as_float(hi);
        }

    const int col0 = n0 + tx * 4;
    const float4 bsv = *reinterpret_cast<const float4*>(bias + col0);
#pragma unroll
    for (int r = 0; r < 8; r++) {
        long row = m0 + ty * 8 + r;
        float4 v;
        v.x = accf[r][0] + bsv.x;
        v.y = accf[r][1] + bsv.y;
        v.z = accf[r][2] + bsv.z;
        v.w = accf[r][3] + bsv.w;
        if (EM == 1) {
            if (col0 < 192) { v.x *= QSCALE; v.y *= QSCALE; v.z *= QSCALE; v.w *= QSCALE; }
        }
        if (EM == 2) {
            float4 rv = *reinterpret_cast<const float4*>(R + row * N + col0);
            v.x += rv.x; v.y += rv.y; v.z += rv.z; v.w += rv.w;
        }
        if (EM == 3) {
            v.x = 0.5f * v.x * (1.0f + erff(v.x * 0.70710678118654752f));
            v.y = 0.5f * v.y * (1.0f + erff(v.y * 0.70710678118654752f));
            v.z = 0.5f * v.z * (1.0f + erff(v.z * 0.70710678118654752f));
            v.w = 0.5f * v.w * (1.0f + erff(v.w * 0.70710678118654752f));
        }
        *reinterpret_cast<float4*>(Y + row * N + col0) = v;
    }
}

// ---------------- spatial window attention: one CTA per (window-frame, head) ----------------
__global__ void __launch_bounds__(128) attn_spatial_kernel(const float* __restrict__ qkv,
                                                           float* __restrict__ osp) {
    __shared__ float qs[49][33], ks[49][33], vs[49][33];
    __shared__ float sc[49][50];
    const int gh = blockIdx.x;
    const int g = gh / 6, h = gh % 6;
    const int b = g >> 9;
    const int rem = g & 511;
    const int win = rem >> 3, t = rem & 7;
    const int wh = win >> 3, ww = win & 7;
    const int tid = threadIdx.x;
    const long frame = (long)(b * 8 + t) * Lv;

    for (int idx = tid; idx < 49 * 32; idx += 128) {
        int i = idx >> 5, j = idx & 31;
        int l = (wh * 7 + i / 7) * 56 + ww * 7 + (i % 7);
        long base = (frame + l) * 576 + h * 32 + j;
        qs[i][j] = qkv[base];
        ks[i][j] = qkv[base + 192];
        vs[i][j] = qkv[base + 384];
    }
    __syncthreads();

    for (int p = tid; p < 49 * 49; p += 128) {
        int i = p / 49, j = p % 49;
        float a = 0.f;
#pragma unroll
        for (int kk = 0; kk < 32; kk++) a += qs[i][kk] * ks[j][kk];
        sc[i][j] = a;
    }
    __syncthreads();

    if (tid < 49) {
        float mx = -1e30f;
#pragma unroll 7
        for (int j = 0; j < 49; j++) mx = fmaxf(mx, sc[tid][j]);
        float sum = 0.f;
#pragma unroll 7
        for (int j = 0; j < 49; j++) { float e = __expf(sc[tid][j] - mx); sc[tid][j] = e; sum += e; }
        float inv = 1.0f / sum;
#pragma unroll 7
        for (int j = 0; j < 49; j++) sc[tid][j] *= inv;
    }
    __syncthreads();

    for (int p = tid; p < 49 * 32; p += 128) {
        int i = p >> 5, j = p & 31;
        float a = 0.f;
#pragma unroll
        for (int n = 0; n < 49; n++) a += sc[i][n] * vs[n][j];
        int l = (wh * 7 + i / 7) * 56 + ww * 7 + (i % 7);
        osp[(frame + l) * 192 + h * 32 + j] = a;
    }
}

// ---------------- temporal attention: one warp per (pixel, head), T=8, d=32=warp ----------------
__global__ void __launch_bounds__(256) attn_temporal_kernel(const float* __restrict__ qkv,
                                                            float* __restrict__ ot) {
    const int unit = blockIdx.x * 8 + (threadIdx.x >> 5);
    const int lane = threadIdx.x & 31;
    const int g = unit / 6, h = unit % 6;
    const int b = g / Lv, l = g % Lv;
    const long base0 = ((long)(b * 8) * Lv + l) * 576 + h * 32 + lane;
    const long tstride = (long)Lv * 576;

    float q[8], k[8], v[8];
#pragma unroll
    for (int t = 0; t < 8; t++) {
        long base = base0 + (long)t * tstride;
        q[t] = qkv[base];
        k[t] = qkv[base + 192];
        v[t] = qkv[base + 384];
    }
    float s[64];
#pragma unroll
    for (int t1 = 0; t1 < 8; t1++)
#pragma unroll
        for (int t2 = 0; t2 < 8; t2++) {
            float p = q[t1] * k[t2];
            p += __shfl_xor_sync(~0u, p, 16);
            p += __shfl_xor_sync(~0u, p, 8);
            p += __shfl_xor_sync(~0u, p, 4);
            p += __shfl_xor_sync(~0u, p, 2);
            p += __shfl_xor_sync(~0u, p, 1);
            s[t1 * 8 + t2] = p;
        }
#pragma unroll
    for (int t1 = 0; t1 < 8; t1++) {
        float mx = s[t1 * 8];
#pragma unroll
        for (int t2 = 1; t2 < 8; t2++) mx = fmaxf(mx, s[t1 * 8 + t2]);
        float sum = 0.f;
#pragma unroll
        for (int t2 = 0; t2 < 8; t2++) { float e = __expf(s[t1 * 8 + t2] - mx); s[t1 * 8 + t2] = e; sum += e; }
        float inv = 1.0f / sum;
#pragma unroll
        for (int t2 = 0; t2 < 8; t2++) s[t1 * 8 + t2] *= inv;
    }
#pragma unroll
    for (int t1 = 0; t1 < 8; t1++) {
        float o = 0.f;
#pragma unroll
        for (int t2 = 0; t2 < 8; t2++) o += s[t1 * 8 + t2] * v[t2];
        ot[((long)(b * 8 + t1) * Lv + l) * 192 + h * 32 + lane] = o;
    }
}

// ---------------- launcher ----------------
extern "C" void kernel_launch(void* const* d_in, const int* in_sizes, int n_in,
                              void* d_out, int out_size) {
    (void)in_sizes; (void)n_in;
    const float* x        = (const float*)d_in[0];
    const float* norm1_g  = (const float*)d_in[2];
    const float* norm1_b  = (const float*)d_in[3];
    const float* qkv_w    = (const float*)d_in[4];
    const float* qkv_b    = (const float*)d_in[5];
    const float* proj_sp_w = (const float*)d_in[6];
    const float* proj_sp_b = (const float*)d_in[7];
    const float* proj_t_w = (const float*)d_in[8];
    const float* proj_t_b = (const float*)d_in[9];
    const float* norm2_g  = (const float*)d_in[10];
    const float* norm2_b  = (const float*)d_in[11];
    const float* te_fc1_w = (const float*)d_in[12];
    const float* te_fc1_b = (const float*)d_in[13];
    const float* te_fc2_w = (const float*)d_in[14];
    const float* te_fc2_b = (const float*)d_in[15];
    const float* sp_fc1_w = (const float*)d_in[16];
    const float* sp_fc1_b = (const float*)d_in[17];
    const float* sp_fc2_w = (const float*)d_in[18];
    const float* sp_fc2_b = (const float*)d_in[19];
    const float* fuse_w   = (const float*)d_in[20];
    const float* fuse_b   = (const float*)d_in[21];

    float* out = (float*)d_out;
    float *xt, *xsp;
    if ((long)out_size >= 3 * MCl) {
        xt = out + MCl;
        xsp = out + 2 * MCl;
    } else {  // harness only wants 'out' — keep branch buffers in scratch
        void* p;
        cudaGetSymbolAddress(&p, g_xt_fb);  xt = (float*)p;
        cudaGetSymbolAddress(&p, g_xsp_fb); xsp = (float*)p;
    }
    void* p;
    cudaGetSymbolAddress(&p, g_qkv);    float* qkv = (float*)p;
    cudaGetSymbolAddress(&p, g_osp);    float* osp = (float*)p;
    cudaGetSymbolAddress(&p, g_ot);     float* otb = (float*)p;
    cudaGetSymbolAddress(&p, g_h);      float* hbuf = (float*)p;
    cudaGetSymbolAddress(&p, g_mean1);  float* mean1 = (float*)p;
    cudaGetSymbolAddress(&p, g_rstd1);  float* rstd1 = (float*)p;
    cudaGetSymbolAddress(&p, g_mean2t); float* mean2t = (float*)p;
    cudaGetSymbolAddress(&p, g_rstd2t); float* rstd2t = (float*)p;
    cudaGetSymbolAddress(&p, g_mean2s); float* mean2s = (float*)p;
    cudaGetSymbolAddress(&p, g_rstd2s); float* rstd2s = (float*)p;

    const dim3 blk(256);
    const int MT = Mv / GBM;  // 1568

    // 1) LN1 stats
    ln_stats_kernel<<<Mv / 8, blk>>>(x, mean1, rstd1);
    // 2) QKV = LN1(x) @ qkv_w^T + b  (q pre-scaled by d^-0.5)
    gemm_kernel<192, 1, 1><<<dim3(MT, 576 / GBN), blk>>>(
        x, nullptr, qkv_w, qkv_b, mean1, rstd1, norm1_g, norm1_b, nullptr, qkv, 576);
    // 3) spatial attention
    attn_spatial_kernel<<<4096 * 6, 128>>>(qkv, osp);
    // 4) temporal attention
    attn_temporal_kernel<<<(Bv * Lv * 6) / 8, 256>>>(qkv, otb);
    // 5) x_sp_res = osp @ proj_sp^T + b + x
    gemm_kernel<192, 0, 2><<<dim3(MT, 3), blk>>>(
        osp, nullptr, proj_sp_w, proj_sp_b, nullptr, nullptr, nullptr, nullptr, x, xsp, 192);
    // 6) x_t_res = ot @ proj_t^T + b + x
    gemm_kernel<192, 0, 2><<<dim3(MT, 3), blk>>>(
        otb, nullptr, proj_t_w, proj_t_b, nullptr, nullptr, nullptr, nullptr, x, xt, 192);
    // 7) LN2 stats for both branches
    ln_stats_kernel<<<Mv / 8, blk>>>(xt, mean2t, rstd2t);
    ln_stats_kernel<<<Mv / 8, blk>>>(xsp, mean2s, rstd2s);
    // 8) temporal MLP: h = gelu(LN2(xt)@fc1^T+b1); xt += h@fc2^T+b2
    gemm_kernel<192, 1, 3><<<dim3(MT, HIDv / GBN), blk>>>(
        xt, nullptr, te_fc1_w, te_fc1_b, mean2t, rstd2t, norm2_g, norm2_b, nullptr, hbuf, HIDv);
    gemm_kernel<768, 0, 2><<<dim3(MT, 3), blk>>>(
        hbuf, nullptr, te_fc2_w, te_fc2_b, nullptr, nullptr, nullptr, nullptr, xt, xt, 192);
    // 9) spatial MLP
    gemm_kernel<192, 1, 3><<<dim3(MT, HIDv / GBN), blk>>>(
        xsp, nullptr, sp_fc1_w, sp_fc1_b, mean2s, rstd2s, norm2_g, norm2_b, nullptr, hbuf, HIDv);
    gemm_kernel<768, 0, 2><<<dim3(MT, 3), blk>>>(
        hbuf, nullptr, sp_fc2_w, sp_fc2_b, nullptr, nullptr, nullptr, nullptr, xsp, xsp, 192);
    // 10) out = [xt | xsp] @ fuse_w^T + fuse_b
    gemm_kernel<384, 2, 0><<<dim3(MT, 3), blk>>>(
        xt, xsp, fuse_w, fuse_b, nullptr, nullptr, nullptr, nullptr, nullptr, out, 192);
}

// round 3
// speedup vs baseline: 1.5726x; 1.5726x over previous
#include <cuda_runtime.h>
#include <cuda_bf16.h>
#include <math.h>
#include <stdint.h>

// ---------------- problem constants ----------------
constexpr int Bv = 8, Tv = 8, Hv = 56, Wv = 56, Cv = 192;
constexpr int NHv = 6, Lv = Hv * Wv;                // 3136
constexpr int HIDv = 4 * Cv;                        // 768
constexpr int Mv = Bv * Tv * Lv;                    // 200704 tokens
constexpr long MCl = (long)Mv * Cv;
constexpr float QSCALE = 0.17677669529663687f;      // 32^-0.5

// ---------------- device scratch ----------------
__device__ float g_mean1[Mv];
__device__ float g_rstd1[Mv];
__device__ float g_mean2t[Mv];
__device__ float g_rstd2t[Mv];
__device__ float g_mean2s[Mv];
__device__ float g_rstd2s[Mv];
__device__ float g_qkv[(long)Mv * 576];
__device__ float g_osp[MCl];
__device__ float g_ot[MCl];
__device__ float g_h[(long)Mv * HIDv];
__device__ float g_xt_fb[MCl];
__device__ float g_xsp_fb[MCl];

// ---------------- helpers ----------------
__device__ __forceinline__ uint32_t smem_u32(const void* p) {
    uint32_t a;
    asm("{ .reg .u64 t; cvta.to.shared.u64 t, %1; cvt.u32.u64 %0, t; }" : "=r"(a) : "l"(p));
    return a;
}

#define LDSM4(r, addr)                                                        \
    asm volatile("ldmatrix.sync.aligned.m8n8.x4.shared.b16 {%0,%1,%2,%3}, [%4];" \
        : "=r"((r)[0]), "=r"((r)[1]), "=r"((r)[2]), "=r"((r)[3]) : "r"(addr))

#define MMA_BF16(c, a, b0, b1)                                                \
    asm volatile("mma.sync.aligned.m16n8k16.row.col.f32.bf16.bf16.f32 "       \
        "{%0,%1,%2,%3},{%4,%5,%6,%7},{%8,%9},{%0,%1,%2,%3};"                  \
        : "+f"((c)[0]), "+f"((c)[1]), "+f"((c)[2]), "+f"((c)[3])              \
        : "r"((a)[0]), "r"((a)[1]), "r"((a)[2]), "r"((a)[3]), "r"(b0), "r"(b1))

// convert float4 -> bf16 hi quad + lo quad, store 8B each (row stride 80B)
__device__ __forceinline__ void cvst80(char* hi, char* lo, int row, int colf, float4 v) {
    uint32_t off = row * 80 + colf * 2;
    uint32_t h01, h23;
    asm("cvt.rn.bf16x2.f32 %0, %1, %2;" : "=r"(h01) : "f"(v.y), "f"(v.x));
    asm("cvt.rn.bf16x2.f32 %0, %1, %2;" : "=r"(h23) : "f"(v.w), "f"(v.z));
    float r0 = v.x - __uint_as_float(h01 << 16);
    float r1 = v.y - __uint_as_float(h01 & 0xFFFF0000u);
    float r2 = v.z - __uint_as_float(h23 << 16);
    float r3 = v.w - __uint_as_float(h23 & 0xFFFF0000u);
    uint32_t l01, l23;
    asm("cvt.rn.bf16x2.f32 %0, %1, %2;" : "=r"(l01) : "f"(r1), "f"(r0));
    asm("cvt.rn.bf16x2.f32 %0, %1, %2;" : "=r"(l23) : "f"(r3), "f"(r2));
    *reinterpret_cast<uint2*>(hi + off) = make_uint2(h01, h23);
    *reinterpret_cast<uint2*>(lo + off) = make_uint2(l01, l23);
}

// ---------------- mma.sync fused GEMM ----------------
// Y[M,N] = epi( f(A)[M,KD] @ W[N,KD]^T + bias )
// AM: 0 plain, 1 layernorm, 2 concat(A|A2) along K (row stride 192 each)
// EM: 0 bias, 1 bias+qscale(cols<192), 2 bias+residual, 3 bias+exact GELU
// smem stage layout (stride-80B rows): Ahi 0 | Alo 10240 | Bhi 20480 | Blo 25600
constexpr int STAGE = 30720;
constexpr int DSMEM = 2 * STAGE;

template <int KD, int AM, int EM>
__global__ void __launch_bounds__(256, 2)
mma_gemm(const float* __restrict__ A, const float* __restrict__ A2,
         const float* __restrict__ W, const float* __restrict__ bias,
         const float* __restrict__ mean, const float* __restrict__ rstd,
         const float* __restrict__ gamma, const float* __restrict__ beta,
         const float* __restrict__ R, float* __restrict__ Y, int N) {
    extern __shared__ char sm[];
    const int tid = threadIdx.x;
    const long m0 = (long)blockIdx.x * 128;
    const int n0 = blockIdx.y * 64;
    constexpr int NS = KD / 32;

    // loader mapping
    const int ar = tid >> 1, ac = (tid & 1) * 16;   // A: 2 thr/row, 4 float4 each
    const int br = tid >> 2, bc = (tid & 3) * 8;    // B: 4 thr/row, 2 float4 each
    float mu = 0.f, rsd = 0.f;
    if (AM == 1) { mu = mean[m0 + ar]; rsd = rstd[m0 + ar]; }

    float4 pa[4], pb[2];
    auto gload = [&](int s) {
        const int kg = s * 32;
#pragma unroll
        for (int j = 0; j < 4; j++) {
            int col = kg + ac + j * 4;
            const float* src;
            if (AM == 2) src = (col < 192) ? A + (m0 + ar) * 192 + col
                                           : A2 + (m0 + ar) * 192 + (col - 192);
            else         src = A + (m0 + ar) * (long)KD + col;
            float4 v = *reinterpret_cast<const float4*>(src);
            if (AM == 1) {
                float4 g4 = *reinterpret_cast<const float4*>(gamma + col);
                float4 b4 = *reinterpret_cast<const float4*>(beta + col);
                v.x = (v.x - mu) * rsd * g4.x + b4.x;
                v.y = (v.y - mu) * rsd * g4.y + b4.y;
                v.z = (v.z - mu) * rsd * g4.z + b4.z;
                v.w = (v.w - mu) * rsd * g4.w + b4.w;
            }
            pa[j] = v;
        }
#pragma unroll
        for (int j = 0; j < 2; j++)
            pb[j] = *reinterpret_cast<const float4*>(W + (long)(n0 + br) * KD + kg + bc + j * 4);
    };
    auto sstore = [&](int buf) {
        char* base = sm + buf * STAGE;
#pragma unroll
        for (int j = 0; j < 4; j++) cvst80(base, base + 10240, ar, ac + j * 4, pa[j]);
#pragma unroll
        for (int j = 0; j < 2; j++) cvst80(base + 20480, base + 25600, br, bc + j * 4, pb[j]);
    };

    // mma mapping: 8 warps = 4(M) x 2(N); warp tile 32x32
    const int l = tid & 31, wid = tid >> 5;
    const int wm = wid & 3, wn = wid >> 2;
    const int arow = wm * 32 + (l & 15);
    const int acol8 = (l >> 4) * 8;
    const int brow = wn * 32 + (l & 7) + ((l >> 4) << 3);
    const int bcol8 = ((l >> 3) & 1) * 8;
    const uint32_t smb = smem_u32(sm);

    float acc[2][4][4];
#pragma unroll
    for (int i = 0; i < 2; i++)
#pragma unroll
        for (int j = 0; j < 4; j++)
#pragma unroll
            for (int k = 0; k < 4; k++) acc[i][j][k] = 0.f;

    auto mmastage = [&](int buf) {
        const uint32_t base = smb + buf * STAGE;
#pragma unroll
        for (int kt = 0; kt < 2; kt++) {
            uint32_t ah[2][4], alr[2][4], bh[2][4], blr[2][4];
#pragma unroll
            for (int mt = 0; mt < 2; mt++) {
                uint32_t addr = base + (arow + mt * 16) * 80 + (kt * 16 + acol8) * 2;
                LDSM4(ah[mt], addr);
                LDSM4(alr[mt], addr + 10240);
            }
#pragma unroll
            for (int nt = 0; nt < 2; nt++) {
                uint32_t addr = base + 20480 + (brow + nt * 16) * 80 + (kt * 16 + bcol8) * 2;
                LDSM4(bh[nt], addr);
                LDSM4(blr[nt], addr + 5120);
            }
#pragma unroll
            for (int mt = 0; mt < 2; mt++)
#pragma unroll
                for (int nn = 0; nn < 4; nn++) {
                    const int nt = nn >> 1, jj = nn & 1;
                    MMA_BF16(acc[mt][nn], ah[mt], bh[nt][2 * jj], bh[nt][2 * jj + 1]);
                    MMA_BF16(acc[mt][nn], ah[mt], blr[nt][2 * jj], blr[nt][2 * jj + 1]);
                    MMA_BF16(acc[mt][nn], alr[mt], bh[nt][2 * jj], bh[nt][2 * jj + 1]);
                }
        }
    };

    gload(0); sstore(0);
    gload(1);
    __syncthreads();
    for (int s = 0; s < NS; s++) {
        mmastage(s & 1);
        __syncthreads();
        if (s + 1 < NS) {
            sstore((s + 1) & 1);
            if (s + 2 < NS) gload(s + 2);
            __syncthreads();
        }
    }

    // register epilogue
    const int g = l >> 2, tg = l & 3;
#pragma unroll
    for (int mt = 0; mt < 2; mt++)
#pragma unroll
        for (int nn = 0; nn < 4; nn++) {
            const int col = n0 + wn * 32 + nn * 8 + 2 * tg;
            const float b0 = bias[col], b1 = bias[col + 1];
#pragma unroll
            for (int h = 0; h < 2; h++) {
                const long row = m0 + wm * 32 + mt * 16 + g + 8 * h;
                float vx = acc[mt][nn][2 * h] + b0;
                float vy = acc[mt][nn][2 * h + 1] + b1;
                if (EM == 1) {
                    if (col < 192) { vx *= QSCALE; vy *= QSCALE; }
                }
                if (EM == 2) {
                    float2 rv = *reinterpret_cast<const float2*>(R + row * (long)N + col);
                    vx += rv.x; vy += rv.y;
                }
                if (EM == 3) {
                    vx = 0.5f * vx * (1.0f + erff(vx * 0.70710678118654752f));
                    vy = 0.5f * vy * (1.0f + erff(vy * 0.70710678118654752f));
                }
                *reinterpret_cast<float2*>(Y + row * (long)N + col) = make_float2(vx, vy);
            }
        }
}

// ---------------- LN statistics ----------------
__global__ void ln_stats_kernel(const float* __restrict__ X,
                                float* __restrict__ mean, float* __restrict__ rstd) {
    int tok = blockIdx.x * 8 + (threadIdx.x >> 5);
    int lane = threadIdx.x & 31;
    const float* p = X + (long)tok * Cv;
    float v[6];
#pragma unroll
    for (int i = 0; i < 6; i++) v[i] = p[lane + i * 32];
    float s = v[0] + v[1] + v[2] + v[3] + v[4] + v[5];
#pragma unroll
    for (int o = 16; o > 0; o >>= 1) s += __shfl_xor_sync(~0u, s, o);
    float mu = s * (1.0f / Cv);
    float qv = 0.f;
#pragma unroll
    for (int i = 0; i < 6; i++) { float d = v[i] - mu; qv += d * d; }
#pragma unroll
    for (int o = 16; o > 0; o >>= 1) qv += __shfl_xor_sync(~0u, qv, o);
    if (lane == 0) {
        mean[tok] = mu;
        rstd[tok] = rsqrtf(qv * (1.0f / Cv) + 1e-5f);
    }
}

// ---------------- spatial window attention ----------------
__global__ void __launch_bounds__(128) attn_spatial_kernel(const float* __restrict__ qkv,
                                                           float* __restrict__ osp) {
    __shared__ float qs[49][33], ks[49][33], vs[49][33];
    __shared__ float sc[49][50];
    const int gh = blockIdx.x;
    const int g = gh / 6, h = gh % 6;
    const int b = g >> 9;
    const int rem = g & 511;
    const int win = rem >> 3, t = rem & 7;
    const int wh = win >> 3, ww = win & 7;
    const int tid = threadIdx.x;
    const long frame = (long)(b * 8 + t) * Lv;

    for (int idx = tid; idx < 49 * 32; idx += 128) {
        int i = idx >> 5, j = idx & 31;
        int l = (wh * 7 + i / 7) * 56 + ww * 7 + (i % 7);
        long base = (frame + l) * 576 + h * 32 + j;
        qs[i][j] = qkv[base];
        ks[i][j] = qkv[base + 192];
        vs[i][j] = qkv[base + 384];
    }
    __syncthreads();

    for (int p = tid; p < 49 * 49; p += 128) {
        int i = p / 49, j = p % 49;
        float a = 0.f;
#pragma unroll
        for (int kk = 0; kk < 32; kk++) a += qs[i][kk] * ks[j][kk];
        sc[i][j] = a;
    }
    __syncthreads();

    if (tid < 49) {
        float mx = -1e30f;
#pragma unroll 7
        for (int j = 0; j < 49; j++) mx = fmaxf(mx, sc[tid][j]);
        float sum = 0.f;
#pragma unroll 7
        for (int j = 0; j < 49; j++) { float e = __expf(sc[tid][j] - mx); sc[tid][j] = e; sum += e; }
        float inv = 1.0f / sum;
#pragma unroll 7
        for (int j = 0; j < 49; j++) sc[tid][j] *= inv;
    }
    __syncthreads();

    for (int p = tid; p < 49 * 32; p += 128) {
        int i = p >> 5, j = p & 31;
        float a = 0.f;
#pragma unroll
        for (int n = 0; n < 49; n++) a += sc[i][n] * vs[n][j];
        int l = (wh * 7 + i / 7) * 56 + ww * 7 + (i % 7);
        osp[(frame + l) * 192 + h * 32 + j] = a;
    }
}

// ---------------- temporal attention ----------------
__global__ void __launch_bounds__(256) attn_temporal_kernel(const float* __restrict__ qkv,
                                                            float* __restrict__ ot) {
    const int unit = blockIdx.x * 8 + (threadIdx.x >> 5);
    const int lane = threadIdx.x & 31;
    const int g = unit / 6, h = unit % 6;
    const int b = g / Lv, l = g % Lv;
    const long base0 = ((long)(b * 8) * Lv + l) * 576 + h * 32 + lane;
    const long tstride = (long)Lv * 576;

    float q[8], k[8], v[8];
#pragma unroll
    for (int t = 0; t < 8; t++) {
        long base = base0 + (long)t * tstride;
        q[t] = qkv[base];
        k[t] = qkv[base + 192];
        v[t] = qkv[base + 384];
    }
    float s[64];
#pragma unroll
    for (int t1 = 0; t1 < 8; t1++)
#pragma unroll
        for (int t2 = 0; t2 < 8; t2++) {
            float p = q[t1] * k[t2];
            p += __shfl_xor_sync(~0u, p, 16);
            p += __shfl_xor_sync(~0u, p, 8);
            p += __shfl_xor_sync(~0u, p, 4);
            p += __shfl_xor_sync(~0u, p, 2);
            p += __shfl_xor_sync(~0u, p, 1);
            s[t1 * 8 + t2] = p;
        }
#pragma unroll
    for (int t1 = 0; t1 < 8; t1++) {
        float mx = s[t1 * 8];
#pragma unroll
        for (int t2 = 1; t2 < 8; t2++) mx = fmaxf(mx, s[t1 * 8 + t2]);
        float sum = 0.f;
#pragma unroll
        for (int t2 = 0; t2 < 8; t2++) { float e = __expf(s[t1 * 8 + t2] - mx); s[t1 * 8 + t2] = e; sum += e; }
        float inv = 1.0f / sum;
#pragma unroll
        for (int t2 = 0; t2 < 8; t2++) s[t1 * 8 + t2] *= inv;
    }
#pragma unroll
    for (int t1 = 0; t1 < 8; t1++) {
        float o = 0.f;
#pragma unroll
        for (int t2 = 0; t2 < 8; t2++) o += s[t1 * 8 + t2] * v[t2];
        ot[((long)(b * 8 + t1) * Lv + l) * 192 + h * 32 + lane] = o;
    }
}

// ---------------- launcher ----------------
extern "C" void kernel_launch(void* const* d_in, const int* in_sizes, int n_in,
                              void* d_out, int out_size) {
    (void)in_sizes; (void)n_in;
    const float* x        = (const float*)d_in[0];
    const float* norm1_g  = (const float*)d_in[2];
    const float* norm1_b  = (const float*)d_in[3];
    const float* qkv_w    = (const float*)d_in[4];
    const float* qkv_b    = (const float*)d_in[5];
    const float* proj_sp_w = (const float*)d_in[6];
    const float* proj_sp_b = (const float*)d_in[7];
    const float* proj_t_w = (const float*)d_in[8];
    const float* proj_t_b = (const float*)d_in[9];
    const float* norm2_g  = (const float*)d_in[10];
    const float* norm2_b  = (const float*)d_in[11];
    const float* te_fc1_w = (const float*)d_in[12];
    const float* te_fc1_b = (const float*)d_in[13];
    const float* te_fc2_w = (const float*)d_in[14];
    const float* te_fc2_b = (const float*)d_in[15];
    const float* sp_fc1_w = (const float*)d_in[16];
    const float* sp_fc1_b = (const float*)d_in[17];
    const float* sp_fc2_w = (const float*)d_in[18];
    const float* sp_fc2_b = (const float*)d_in[19];
    const float* fuse_w   = (const float*)d_in[20];
    const float* fuse_b   = (const float*)d_in[21];

    float* out = (float*)d_out;
    float *xt, *xsp;
    if ((long)out_size >= 3 * MCl) {
        xt = out + MCl;
        xsp = out + 2 * MCl;
    } else {
        void* p;
        cudaGetSymbolAddress(&p, g_xt_fb);  xt = (float*)p;
        cudaGetSymbolAddress(&p, g_xsp_fb); xsp = (float*)p;
    }
    void* p;
    cudaGetSymbolAddress(&p, g_qkv);    float* qkv = (float*)p;
    cudaGetSymbolAddress(&p, g_osp);    float* osp = (float*)p;
    cudaGetSymbolAddress(&p, g_ot);     float* otb = (float*)p;
    cudaGetSymbolAddress(&p, g_h);      float* hbuf = (float*)p;
    cudaGetSymbolAddress(&p, g_mean1);  float* mean1 = (float*)p;
    cudaGetSymbolAddress(&p, g_rstd1);  float* rstd1 = (float*)p;
    cudaGetSymbolAddress(&p, g_mean2t); float* mean2t = (float*)p;
    cudaGetSymbolAddress(&p, g_rstd2t); float* rstd2t = (float*)p;
    cudaGetSymbolAddress(&p, g_mean2s); float* mean2s = (float*)p;
    cudaGetSymbolAddress(&p, g_rstd2s); float* rstd2s = (float*)p;

    cudaFuncSetAttribute(mma_gemm<192, 1, 1>, cudaFuncAttributeMaxDynamicSharedMemorySize, DSMEM);
    cudaFuncSetAttribute(mma_gemm<192, 0, 2>, cudaFuncAttributeMaxDynamicSharedMemorySize, DSMEM);
    cudaFuncSetAttribute(mma_gemm<192, 1, 3>, cudaFuncAttributeMaxDynamicSharedMemorySize, DSMEM);
    cudaFuncSetAttribute(mma_gemm<768, 0, 2>, cudaFuncAttributeMaxDynamicSharedMemorySize, DSMEM);
    cudaFuncSetAttribute(mma_gemm<384, 2, 0>, cudaFuncAttributeMaxDynamicSharedMemorySize, DSMEM);

    const int MT = Mv / 128;  // 1568

    // 1) LN1 stats
    ln_stats_kernel<<<Mv / 8, 256>>>(x, mean1, rstd1);
    // 2) QKV = LN1(x) @ qkv_w^T + b (q pre-scaled)
    mma_gemm<192, 1, 1><<<dim3(MT, 9), 256, DSMEM>>>(
        x, nullptr, qkv_w, qkv_b, mean1, rstd1, norm1_g, norm1_b, nullptr, qkv, 576);
    // 3) spatial attention
    attn_spatial_kernel<<<4096 * 6, 128>>>(qkv, osp);
    // 4) temporal attention
    attn_temporal_kernel<<<(Bv * Lv * 6) / 8, 256>>>(qkv, otb);
    // 5) x_sp = osp @ proj_sp^T + b + x
    mma_gemm<192, 0, 2><<<dim3(MT, 3), 256, DSMEM>>>(
        osp, nullptr, proj_sp_w, proj_sp_b, nullptr, nullptr, nullptr, nullptr, x, xsp, 192);
    // 6) x_t = ot @ proj_t^T + b + x
    mma_gemm<192, 0, 2><<<dim3(MT, 3), 256, DSMEM>>>(
        otb, nullptr, proj_t_w, proj_t_b, nullptr, nullptr, nullptr, nullptr, x, xt, 192);
    // 7) LN2 stats
    ln_stats_kernel<<<Mv / 8, 256>>>(xt, mean2t, rstd2t);
    ln_stats_kernel<<<Mv / 8, 256>>>(xsp, mean2s, rstd2s);
    // 8) temporal MLP
    mma_gemm<192, 1, 3><<<dim3(MT, 12), 256, DSMEM>>>(
        xt, nullptr, te_fc1_w, te_fc1_b, mean2t, rstd2t, norm2_g, norm2_b, nullptr, hbuf, HIDv);
    mma_gemm<768, 0, 2><<<dim3(MT, 3), 256, DSMEM>>>(
        hbuf, nullptr, te_fc2_w, te_fc2_b, nullptr, nullptr, nullptr, nullptr, xt, xt, 192);
    // 9) spatial MLP
    mma_gemm<192, 1, 3><<<dim3(MT, 12), 256, DSMEM>>>(
        xsp, nullptr, sp_fc1_w, sp_fc1_b, mean2s, rstd2s, norm2_g, norm2_b, nullptr, hbuf, HIDv);
    mma_gemm<768, 0, 2><<<dim3(MT, 3), 256, DSMEM>>>(
        hbuf, nullptr, sp_fc2_w, sp_fc2_b, nullptr, nullptr, nullptr, nullptr, xsp, xsp, 192);
    // 10) out = [xt | xsp] @ fuse_w^T + fuse_b
    mma_gemm<384, 2, 0><<<dim3(MT, 3), 256, DSMEM>>>(
        xt, xsp, fuse_w, fuse_b, nullptr, nullptr, nullptr, nullptr, nullptr, out, 192);
}